// round 1
// baseline (speedup 1.0000x reference)
#include <cuda_runtime.h>
#include <cuda_bf16.h>

// Problem constants (fixed shapes for this dataset)
#define M_ROWS   2048
#define N_LAT    8192
#define DIM      256
#define ROWS_CTA 16          // rows per CTA
#define LAT_SLICE 1024       // latents per CTA (slice)
#define LAT_CHUNK 256        // latents per inner iteration (== blockDim)
#define DCHUNK   16          // d elements staged per step
#define NSTAGE   (DIM / DCHUNK)      // 16
#define NCHUNK   (LAT_SLICE / LAT_CHUNK) // 4
#define NSLICE   (N_LAT / LAT_SLICE)     // 8

typedef unsigned long long ull;

// scratch (static device arrays — no allocation)
__device__ float g_cand[M_ROWS * NSLICE * 4];   // per (row, slice): 4 smallest candidates
__device__ float g_tail[M_ROWS];

static __device__ __forceinline__ ull pk(float a, float b) {
    return (ull)__float_as_uint(a) | ((ull)__float_as_uint(b) << 32);
}

// packed |lat + (-row)| accumulate:  A += abs2(R + L)   (R holds negated rows)
#define ABSACC(A, R, L) do {                                        \
    ull _d;                                                         \
    asm("add.rn.f32x2 %0, %1, %2;" : "=l"(_d) : "l"(R), "l"(L));    \
    _d &= 0x7fffffff7fffffffULL;                                    \
    asm("add.rn.f32x2 %0, %1, %2;" : "=l"(A) : "l"(A), "l"(_d));    \
} while (0)

static __device__ __forceinline__ void ins4(float v, float& m0, float& m1, float& m2, float& m3) {
    // keep 4 smallest; m0<=m1<=m2<=m3 invariant
    if (v < m3) {
        float c2 = fminf(v,  m2), d3 = fmaxf(v,  m2);
        float c1 = fminf(c2, m1), d2 = fmaxf(c2, m1);
        float c0 = fminf(c1, m0), d1 = fmaxf(c1, m0);
        m0 = c0; m1 = d1; m2 = d2; m3 = d3;
    }
}

static __device__ __forceinline__ float huber1(float x) {
    // x >= 0 here; HuberLoss(pred=x, target=0), delta=1
    return (x < 1.0f) ? (0.5f * x * x) : (x - 0.5f);
}

// ---------------------------------------------------------------------------
// Kernel 1: L1 cdist + per-(row, slice) smallest-4 candidates
// grid (M_ROWS/ROWS_CTA = 128, NSLICE = 8), block 256
// ---------------------------------------------------------------------------
__global__ void __launch_bounds__(256, 2)
k1_cdist_min4(const float* __restrict__ space, const float* __restrict__ lat) {
    __shared__ ull rowS[(DIM / 2) * ROWS_CTA];     // [128 dpairs][16 rows]  16KB (negated rows)
    __shared__ ull latS[(DCHUNK / 2) * LAT_CHUNK]; // [8 dpairs][256 lats]   16KB

    const int tid = threadIdx.x;
    const int rowBase = blockIdx.x * ROWS_CTA;
    const int slice = blockIdx.y;
    const int r0 = (tid >> 6) * 4;   // 0,4,8,12
    const int c0 = tid & 63;         // latent column group; latents c0 + 64*j

    // ---- stage rows once (negated, d-pair major) ----
    {
        const float* srow = space + rowBase * DIM;
        #pragma unroll
        for (int k = 0; k < 4; ++k) {
            int f4 = tid + k * 256;          // 1024 float4 = 16 rows * 64
            int r  = f4 >> 6;
            int dd = (f4 & 63) << 2;
            float4 v = *reinterpret_cast<const float4*>(srow + r * DIM + dd);
            rowS[(dd >> 1) * ROWS_CTA + r]       = pk(-v.x, -v.y);
            rowS[((dd >> 1) + 1) * ROWS_CTA + r] = pk(-v.z, -v.w);
        }
    }

    float m[4][4];   // running 4-smallest per owned row
    #pragma unroll
    for (int i = 0; i < 4; ++i)
        #pragma unroll
        for (int k = 0; k < 4; ++k) m[i][k] = 1e30f;

    for (int chunk = 0; chunk < NCHUNK; ++chunk) {
        const int nb = slice * LAT_SLICE + chunk * LAT_CHUNK;
        const float* lp = lat + (size_t)(nb + tid) * DIM;   // this thread's staged latent row

        ull acc[4][4];
        #pragma unroll
        for (int i = 0; i < 4; ++i)
            #pragma unroll
            for (int j = 0; j < 4; ++j) acc[i][j] = 0ULL;

        // preload stage 0
        float4 rg[4];
        #pragma unroll
        for (int j = 0; j < 4; ++j)
            rg[j] = reinterpret_cast<const float4*>(lp)[j];

        for (int s = 0; s < NSTAGE; ++s) {
            __syncthreads();   // previous compute done before overwriting latS
            #pragma unroll
            for (int j = 0; j < 4; ++j) {
                latS[(2 * j) * LAT_CHUNK + tid]     = pk(rg[j].x, rg[j].y);
                latS[(2 * j + 1) * LAT_CHUNK + tid] = pk(rg[j].z, rg[j].w);
            }
            __syncthreads();

            if (s + 1 < NSTAGE) {   // prefetch next stage while computing
                const float4* np = reinterpret_cast<const float4*>(lp + (s + 1) * DCHUNK);
                #pragma unroll
                for (int j = 0; j < 4; ++j) rg[j] = np[j];
            }

            #pragma unroll
            for (int dp = 0; dp < DCHUNK / 2; ++dp) {
                const ull* rp = rowS + (s * (DCHUNK / 2) + dp) * ROWS_CTA + r0;
                ulonglong2 ra = *reinterpret_cast<const ulonglong2*>(rp);
                ulonglong2 rb = *reinterpret_cast<const ulonglong2*>(rp + 2);
                ull rv0 = ra.x, rv1 = ra.y, rv2 = rb.x, rv3 = rb.y;
                const ull* cp = latS + dp * LAT_CHUNK + c0;
                ull lv0 = cp[0], lv1 = cp[64], lv2 = cp[128], lv3 = cp[192];

                ABSACC(acc[0][0], rv0, lv0); ABSACC(acc[0][1], rv0, lv1);
                ABSACC(acc[0][2], rv0, lv2); ABSACC(acc[0][3], rv0, lv3);
                ABSACC(acc[1][0], rv1, lv0); ABSACC(acc[1][1], rv1, lv1);
                ABSACC(acc[1][2], rv1, lv2); ABSACC(acc[1][3], rv1, lv3);
                ABSACC(acc[2][0], rv2, lv0); ABSACC(acc[2][1], rv2, lv1);
                ABSACC(acc[2][2], rv2, lv2); ABSACC(acc[2][3], rv2, lv3);
                ABSACC(acc[3][0], rv3, lv0); ABSACC(acc[3][1], rv3, lv1);
                ABSACC(acc[3][2], rv3, lv2); ABSACC(acc[3][3], rv3, lv3);
            }
        }

        // fold packed halves -> distances; update min-4
        #pragma unroll
        for (int i = 0; i < 4; ++i) {
            #pragma unroll
            for (int j = 0; j < 4; ++j) {
                float lo = __uint_as_float((unsigned)(acc[i][j] & 0xffffffffULL));
                float hi = __uint_as_float((unsigned)(acc[i][j] >> 32));
                ins4(lo + hi, m[i][0], m[i][1], m[i][2], m[i][3]);
            }
        }
    }

    // ---- CTA merge: 64 column-threads * 4 candidates per row -> top-4 ----
    __syncthreads();
    float* mb = reinterpret_cast<float*>(latS);   // 16*64*4 floats = 16KB, reuse latS
    #pragma unroll
    for (int i = 0; i < 4; ++i)
        #pragma unroll
        for (int k = 0; k < 4; ++k)
            mb[(r0 + i) * 256 + c0 * 4 + k] = m[i][k];
    __syncthreads();

    if (tid < ROWS_CTA) {
        float t0 = 1e30f, t1 = 1e30f, t2 = 1e30f, t3 = 1e30f;
        const float* p = mb + tid * 256;
        for (int q = 0; q < 256; ++q) ins4(p[q], t0, t1, t2, t3);
        float* dst = g_cand + ((size_t)(rowBase + tid) * NSLICE + slice) * 4;
        dst[0] = t0; dst[1] = t1; dst[2] = t2; dst[3] = t3;
    }
}

// ---------------------------------------------------------------------------
// Kernel 2: merge slices -> tail_dists[row] = mean of 4 smallest
// ---------------------------------------------------------------------------
__global__ void k2_merge_tail() {
    int idx = blockIdx.x * blockDim.x + threadIdx.x;
    if (idx >= M_ROWS) return;
    const float* p = g_cand + (size_t)idx * NSLICE * 4;
    float m0 = 1e30f, m1 = 1e30f, m2 = 1e30f, m3 = 1e30f;
    #pragma unroll
    for (int q = 0; q < NSLICE * 4; ++q) ins4(p[q], m0, m1, m2, m3);
    g_tail[idx] = (m0 + m1 + m2 + m3) * 0.25f;
}

// ---------------------------------------------------------------------------
// Kernel 3: top-64 largest of tail[2048] via bit binary search, huber mean
// (distances are positive -> float bits are order-monotone as unsigned)
// ---------------------------------------------------------------------------
__global__ void k3_top64_huber(float* __restrict__ out) {
    __shared__ int   wred[8];
    __shared__ float wfred[8];
    __shared__ unsigned s_lo, s_hi;
    __shared__ int   s_ngt;
    const int t = threadIdx.x;   // 256 threads, 8 values each

    unsigned b[8];
    #pragma unroll
    for (int k = 0; k < 8; ++k) b[k] = __float_as_uint(g_tail[t + 256 * k]);

    if (t == 0) { s_lo = 0u; s_hi = 0x7f800000u; }
    __syncthreads();
    unsigned lo = s_lo, hi = s_hi;

    // find lo = bit pattern of the 64th-largest value:
    // largest u with count(bits >= u) >= 64
    while (hi - lo > 1u) {
        unsigned mid = lo + ((hi - lo) >> 1);
        int c = 0;
        #pragma unroll
        for (int k = 0; k < 8; ++k) c += (b[k] >= mid);
        #pragma unroll
        for (int o = 16; o; o >>= 1) c += __shfl_down_sync(0xffffffffu, c, o);
        if ((t & 31) == 0) wred[t >> 5] = c;
        __syncthreads();
        if (t == 0) {
            int tot = 0;
            #pragma unroll
            for (int w = 0; w < 8; ++w) tot += wred[w];
            if (tot >= 64) s_lo = mid; else s_hi = mid;
        }
        __syncthreads();
        lo = s_lo; hi = s_hi;
        __syncthreads();
    }

    // sum huber over strictly-greater values; count them
    int c = 0; float hs = 0.0f;
    #pragma unroll
    for (int k = 0; k < 8; ++k) {
        if (b[k] > lo) { ++c; hs += huber1(__uint_as_float(b[k])); }
    }
    #pragma unroll
    for (int o = 16; o; o >>= 1) {
        c  += __shfl_down_sync(0xffffffffu, c, o);
        hs += __shfl_down_sync(0xffffffffu, hs, o);
    }
    if ((t & 31) == 0) { wred[t >> 5] = c; wfred[t >> 5] = hs; }
    __syncthreads();
    if (t == 0) {
        int ngt = 0; float tot = 0.0f;
        #pragma unroll
        for (int w = 0; w < 8; ++w) { ngt += wred[w]; tot += wfred[w]; }
        float tv = __uint_as_float(lo);
        out[0] = (tot + (float)(64 - ngt) * huber1(tv)) * (1.0f / 64.0f);
    }
}

// ---------------------------------------------------------------------------
extern "C" void kernel_launch(void* const* d_in, const int* in_sizes, int n_in,
                              void* d_out, int out_size) {
    const float* a = (const float*)d_in[0];
    const float* b = (const float*)d_in[1];
    const float *space, *lats;
    if (in_sizes[0] == M_ROWS * DIM) { space = a; lats = b; }
    else                             { space = b; lats = a; }

    dim3 g1(M_ROWS / ROWS_CTA, NSLICE);   // 128 x 8
    k1_cdist_min4<<<g1, 256>>>(space, lats);
    k2_merge_tail<<<(M_ROWS + 255) / 256, 256>>>();
    k3_top64_huber<<<1, 256>>>((float*)d_out);
}